// round 15
// baseline (speedup 1.0000x reference)
#include <cuda_runtime.h>
#include <cuda_fp16.h>
#include <cstdint>

// Problem constants (fixed by the dataset)
#define Bq   2
#define Sq   2048
#define Hd   2048
#define HQn  16
#define HKVn 4
#define Dh   128
#define NREP (HQn / HKVn)

// Scratch (device globals; no runtime allocation allowed) — fp16 dataflow
__device__ __half g_qH[(size_t)Bq * Sq * HQn * Dh];     // 16 MB
__device__ __half g_kH[(size_t)Bq * Sq * HKVn * Dh];    // 4 MB
__device__ __half g_vH[(size_t)Bq * Sq * HKVn * Dh];    // 4 MB
__device__ __half g_ctxH[(size_t)Bq * Sq * HQn * Dh];   // 16 MB
__device__ __half g_hidH[(size_t)Bq * Sq * Hd];         // 16 MB
__device__ __half g_WqkvT[(size_t)3072 * 2048];         // 12 MB
__device__ __half g_WoT[(size_t)2048 * 2048];           // 8 MB
__device__ __half g_vT[(size_t)Bq * HKVn * Dh * Sq];    // 4 MB

// ---------------------------------------------------------------------------
// Helpers
// ---------------------------------------------------------------------------
__device__ __forceinline__ uint32_t smem_to_u32(const void* p) {
    uint32_t a;
    asm("{ .reg .u64 t; cvta.to.shared.u64 t, %1; cvt.u32.u64 %0, t; }"
        : "=r"(a) : "l"(p));
    return a;
}

__device__ __forceinline__ void mma_f16(float* d, const uint32_t* a,
                                        const uint32_t* b) {
    asm volatile(
        "mma.sync.aligned.m16n8k16.row.col.f32.f16.f16.f32 "
        "{%0,%1,%2,%3}, {%4,%5,%6,%7}, {%8,%9}, {%0,%1,%2,%3};"
        : "+f"(d[0]), "+f"(d[1]), "+f"(d[2]), "+f"(d[3])
        : "r"(a[0]), "r"(a[1]), "r"(a[2]), "r"(a[3]), "r"(b[0]), "r"(b[1]));
}

__device__ __forceinline__ void cpa16(uint32_t dst, const void* src) {
    asm volatile("cp.async.cg.shared.global [%0], [%1], 16;"
                 :: "r"(dst), "l"(src) : "memory");
}
#define CP_COMMIT() asm volatile("cp.async.commit_group;" ::: "memory")
#define CP_WAIT0()  asm volatile("cp.async.wait_group 0;" ::: "memory")
#define CP_WAIT1()  asm volatile("cp.async.wait_group 1;" ::: "memory")

// ---------------------------------------------------------------------------
// Fused prep, ONE launch: hidden fp32->fp16 cvt + all 4 weight transposes.
// ---------------------------------------------------------------------------
#define CVT_N4     (Bq * Sq * Hd / 4)          // 2097152
#define CVT_BLOCKS (CVT_N4 / 256)              // 8192
#define TRB_PER_W  2048
#define TR_BLOCKS  (4 * TRB_PER_W)             // 8192

__global__ void prep_kernel(const float* __restrict__ hidden,
                            __half* __restrict__ hidH,
                            const float* __restrict__ Wq,
                            const float* __restrict__ Wk,
                            const float* __restrict__ Wv,
                            const float* __restrict__ Wo,
                            __half* __restrict__ wqkvT,
                            __half* __restrict__ woT) {
    if (blockIdx.x < CVT_BLOCKS) {
        const int i = blockIdx.x * 256 + threadIdx.x;
        float4 x = ((const float4*)hidden)[i];
        ((__half2*)hidH)[2 * i]     = __floats2half2_rn(x.x, x.y);
        ((__half2*)hidH)[2 * i + 1] = __floats2half2_rn(x.z, x.w);
        return;
    }
    const int bid = blockIdx.x - CVT_BLOCKS;
    const int z = bid / TRB_PER_W;
    const float* in;
    __half* out;
    int C;
    if (z == 0)      { in = Wq; out = wqkvT;                       C = 2048; }
    else if (z == 1) { in = Wk; out = wqkvT + (size_t)2048 * 2048; C = 512; }
    else if (z == 2) { in = Wv; out = wqkvT + (size_t)2560 * 2048; C = 512; }
    else             { in = Wo; out = woT;                         C = 2048; }
    const int lb = bid % TRB_PER_W;
    const int bx = (lb & 63) * 32;
    const int by = (lb >> 6) * 64;
    if (bx >= C) return;

    __shared__ float t[64][33];
    const int x = threadIdx.x & 31, y = threadIdx.x >> 5;
#pragma unroll
    for (int j = 0; j < 64; j += 8)
        t[y + j][x] = in[(size_t)(by + y + j) * C + bx + x];
    __syncthreads();
#pragma unroll
    for (int jj = 0; jj < 4; jj++) {
        const int oc = y * 4 + jj;
        __half* orow = out + (size_t)(bx + oc) * 2048 + by;
        orow[x]      = __float2half(t[x][oc]);
        orow[32 + x] = __float2half(t[32 + x][oc]);
    }
}

// ---------------------------------------------------------------------------
// PERSISTENT FP16 m16n8k16 GEMM, 3-stage cp.async pipeline.
// CTA tile 128x64 (halved N to cut per-SM tile quantization tail).
// 8 warps: wm = (wid&1)*64, wn = (wid>>1)*16; warp tile 64x16, acc[4][2][4].
// ---------------------------------------------------------------------------
#define NST  3
#define STWA 2560                              // A stage words (128 rows x 20)
#define STWB 1280                              // B stage words (64 rows x 20)
#define GEMM_SMEM ((NST * (STWA + STWB)) * 4)  // 46080 B

template <int QKV, typename CT>
__global__ void __launch_bounds__(256, 2)
gemm_f16(const __half* __restrict__ A, const __half* __restrict__ Bt, int K,
         int ntiles, int nx,
         CT* __restrict__ C0, CT* __restrict__ C1, CT* __restrict__ C2) {
    extern __shared__ uint32_t smw[];
    const uint32_t smu = smem_to_u32(smw);

    const int tid = threadIdx.x;
    const int lane = tid & 31, wid = tid >> 5;
    const int wm = (wid & 1) * 64, wn = (wid >> 1) * 16;
    const int g = lane >> 2, tg = lane & 3;

    const int rowj[2] = {tid >> 2, (tid >> 2) + 64};   // A rows (128)
    const int rowB   = tid >> 2;                       // B row (64)
    const int c8 = (tid & 3) * 8;                      // halves offset

    const uint32_t stA = STWA * 4;
    const uint32_t stB2 = STWB * 4;
    uint32_t dA[2];
#pragma unroll
    for (int j = 0; j < 2; j++)
        dA[j] = smu + (uint32_t)(rowj[j] * 20 + c8 / 2) * 4;
    const uint32_t dB = smu + (uint32_t)(NST * STWA + rowB * 20 + c8 / 2) * 4;

    const int nk = K / 32;

    for (int t = blockIdx.x; t < ntiles; t += gridDim.x) {
        const int m0 = (t / nx) * 128, n0 = (t % nx) * 64;
        const __half* Ab = A + (size_t)m0 * K;
        const __half* Bb = Bt + (size_t)n0 * K;

        CP_WAIT0();
        __syncthreads();

#pragma unroll
        for (int p = 0; p < NST - 1; p++) {
            const size_t kk = (size_t)p * 32 + c8;
#pragma unroll
            for (int j = 0; j < 2; j++)
                cpa16(dA[j] + p * stA, Ab + (size_t)rowj[j] * K + kk);
            cpa16(dB + p * stB2, Bb + (size_t)rowB * K + kk);
            CP_COMMIT();
        }

        float acc[4][2][4];
#pragma unroll
        for (int mi = 0; mi < 4; mi++)
#pragma unroll
            for (int ni = 0; ni < 2; ni++)
#pragma unroll
                for (int e = 0; e < 4; e++) acc[mi][ni][e] = 0.f;

        for (int kt = 0; kt < nk; kt++) {
            CP_WAIT1();
            __syncthreads();

            const int kf = kt + NST - 1;
            if (kf < nk) {
                const int s = kf % NST;
                const size_t kk = (size_t)kf * 32 + c8;
#pragma unroll
                for (int j = 0; j < 2; j++)
                    cpa16(dA[j] + s * stA, Ab + (size_t)rowj[j] * K + kk);
                cpa16(dB + s * stB2, Bb + (size_t)rowB * K + kk);
            }
            CP_COMMIT();

            const uint32_t* aw = smw + (kt % NST) * STWA;
            const uint32_t* bw = smw + NST * STWA + (kt % NST) * STWB;
#pragma unroll
            for (int ks = 0; ks < 2; ks++) {
                const int kb = ks * 8;
                uint32_t af[4][4], bf[2][2];
#pragma unroll
                for (int mi = 0; mi < 4; mi++) {
                    const uint32_t* p = &aw[(wm + mi * 16 + g) * 20 + kb + tg];
                    af[mi][0] = p[0];
                    af[mi][1] = p[8 * 20];
                    af[mi][2] = p[4];
                    af[mi][3] = p[8 * 20 + 4];
                }
#pragma unroll
                for (int ni = 0; ni < 2; ni++) {
                    const uint32_t* p = &bw[(wn + ni * 8 + g) * 20 + kb + tg];
                    bf[ni][0] = p[0];
                    bf[ni][1] = p[4];
                }
#pragma unroll
                for (int mi = 0; mi < 4; mi++)
#pragma unroll
                    for (int ni = 0; ni < 2; ni++)
                        mma_f16(acc[mi][ni], af[mi], bf[ni]);
            }
        }

        CT* C;
        int ldc, col0;
        if (QKV) {
            if (n0 < 2048)      { C = C0; ldc = 2048; col0 = n0; }
            else if (n0 < 2560) { C = C1; ldc = 512;  col0 = n0 - 2048; }
            else                { C = C2; ldc = 512;  col0 = n0 - 2560; }
        } else {
            C = C0; ldc = 2048; col0 = n0;
        }
#pragma unroll
        for (int mi = 0; mi < 4; mi++) {
            const int row0 = m0 + wm + mi * 16 + g;
#pragma unroll
            for (int ni = 0; ni < 2; ni++) {
                const int col = col0 + wn + ni * 8 + tg * 2;
                if constexpr (sizeof(CT) == 2) {
                    *(__half2*)&C[(size_t)row0 * ldc + col] =
                        __floats2half2_rn(acc[mi][ni][0], acc[mi][ni][1]);
                    *(__half2*)&C[(size_t)(row0 + 8) * ldc + col] =
                        __floats2half2_rn(acc[mi][ni][2], acc[mi][ni][3]);
                } else {
                    *(float2*)&C[(size_t)row0 * ldc + col] =
                        make_float2(acc[mi][ni][0], acc[mi][ni][1]);
                    *(float2*)&C[(size_t)(row0 + 8) * ldc + col] =
                        make_float2(acc[mi][ni][2], acc[mi][ni][3]);
                }
            }
        }
    }
}

// ---------------------------------------------------------------------------
// Post-QKV fixup, ONE launch (unchanged, passing).
// ---------------------------------------------------------------------------
#define NQROWS (Bq * Sq * HQn)
#define NKROWS (Bq * Sq * HKVn)
#define NORM_BLOCKS ((NQROWS + NKROWS) / 8)
#define VT_BLOCKS   (4 * 64 * Bq * HKVn)

__global__ void postqkv_kernel(__half* __restrict__ qx,
                               __half* __restrict__ kx,
                               const __half* __restrict__ v,
                               __half* __restrict__ vt,
                               const float* __restrict__ qw,
                               const float* __restrict__ kw,
                               const float* __restrict__ cosb,
                               const float* __restrict__ sinb,
                               float qscale) {
    if (blockIdx.x < NORM_BLOCKS) {
        const int row = blockIdx.x * 8 + (threadIdx.x >> 5);
        const int l   = threadIdx.x & 31;

        __half* x;
        const float* w;
        float scale;
        int r, nheads;
        if (row < NQROWS) { x = qx; w = qw; scale = qscale; r = row; nheads = HQn; }
        else              { x = kx; w = kw; scale = 1.0f;  r = row - NQROWS; nheads = HKVn; }
        const int s = (r / nheads) % Sq;

        __half2* rp = (__half2*)(x + (size_t)r * Dh);
        float2 a = __half22float2(rp[l]);
        float2 b = __half22float2(rp[l + 32]);

        float ss = a.x * a.x + a.y * a.y + b.x * b.x + b.y * b.y;
#pragma unroll
        for (int off = 16; off > 0; off >>= 1)
            ss += __shfl_xor_sync(0xffffffffu, ss, off);
        const float rinv = rsqrtf(ss * (1.0f / Dh) + 1e-6f);

        const float2 wa = *(const float2*)&w[2 * l];
        const float2 wb = *(const float2*)&w[64 + 2 * l];
        const float xa0 = a.x * rinv * wa.x, xa1 = a.y * rinv * wa.y;
        const float xb0 = b.x * rinv * wb.x, xb1 = b.y * rinv * wb.y;

        const float* cb = cosb + (size_t)s * Dh;
        const float* sb = sinb + (size_t)s * Dh;
        const float2 ca = *(const float2*)&cb[2 * l];
        const float2 cb2 = *(const float2*)&cb[64 + 2 * l];
        const float2 sa = *(const float2*)&sb[2 * l];
        const float2 sb2 = *(const float2*)&sb[64 + 2 * l];

        const float oa0 = (xa0 * ca.x - xb0 * sa.x) * scale;
        const float oa1 = (xa1 * ca.y - xb1 * sa.y) * scale;
        const float ob0 = (xb0 * cb2.x + xa0 * sb2.x) * scale;
        const float ob1 = (xb1 * cb2.y + xa1 * sb2.y) * scale;

        rp[l]      = __floats2half2_rn(oa0, oa1);
        rp[l + 32] = __floats2half2_rn(ob0, ob1);
    } else {
        const int bid = blockIdx.x - NORM_BLOCKS;
        const int d0 = (bid & 3) * 32;
        const int s0 = ((bid >> 2) & 63) * 32;
        const int z  = bid >> 8;
        const int b = z >> 2, hkv = z & 3;
        const int x = threadIdx.x & 31, y = threadIdx.x >> 5;

        __shared__ __half t[32][34];
        const __half* src = v + (size_t)b * Sq * 512 + hkv * 128;
#pragma unroll
        for (int j = 0; j < 32; j += 8)
            t[y + j][x] = src[(size_t)(s0 + y + j) * 512 + d0 + x];
        __syncthreads();
        __half* dst = vt + ((size_t)z * 128 + d0) * Sq + s0;
#pragma unroll
        for (int j = 0; j < 32; j += 8)
            dst[(size_t)(y + j) * Sq + x] = t[x][y + j];
    }
}

// ---------------------------------------------------------------------------
// Flash attention (round-14 exact: Q-regs, P-alias, exp2 softmax, LPT grid).
// ---------------------------------------------------------------------------
#define FBQ   64
#define FBKV  64
#define KW_S  68
#define VW_S  36
#define OFFW_K0 0
#define KW_STG  (FBKV * KW_S)          // 4352 words
#define OFFW_V0 (2 * KW_STG)           // 8704
#define VW_STG  (Dh * VW_S)            // 4608
#define FLASH_SMEM ((OFFW_V0 + 2 * VW_STG) * 4)   // 71680 B

__global__ void __launch_bounds__(128, 3)
flash_mma_kernel(const __half* __restrict__ q,
                 const __half* __restrict__ k,
                 const __half* __restrict__ vt,
                 __half* __restrict__ ctx) {
    extern __shared__ uint32_t fsw[];
    const uint32_t fsb = smem_to_u32(fsw);

    const int bid = blockIdx.x;
    const int bh  = bid & 31;
    const int q0  = (31 - (bid >> 5)) * FBQ;
    const int b   = bh / HQn;
    const int h   = bh % HQn;
    const int hkv = h / NREP;

    const int tid  = threadIdx.x;
    const int lane = tid & 31, wid = tid >> 5;
    const int g = lane >> 2, tg = lane & 3;
    const int wband = wid * 16;

    const __half* kbase = k + ((size_t)b * Sq * HKVn + hkv) * Dh;
    const __half* vbase = vt + (size_t)(b * HKVn + hkv) * Dh * Sq;

#pragma unroll
    for (int j = 0; j < 8; j++) {
        const int f = tid + j * 128;
        const int rk = f >> 4, ckw = (f & 15) * 4;
        cpa16(fsb + (uint32_t)(OFFW_K0 + rk * KW_S + ckw) * 4,
              kbase + (size_t)rk * HKVn * Dh + ckw * 2);
        const int rv = f >> 3, cvw = (f & 7) * 4;
        cpa16(fsb + (uint32_t)(OFFW_V0 + rv * VW_S + cvw) * 4,
              vbase + (size_t)rv * Sq + cvw * 2);
    }
    CP_COMMIT();

    uint32_t qa[8][4];
    {
        const __half* qr0 = q + (((size_t)b * Sq + q0 + wband + g) * HQn + h) * Dh;
        const __half* qr1 = qr0 + (size_t)8 * HQn * Dh;
#pragma unroll
        for (int ks = 0; ks < 8; ks++) {
            qa[ks][0] = *(const uint32_t*)(qr0 + 16 * ks + 2 * tg);
            qa[ks][1] = *(const uint32_t*)(qr1 + 16 * ks + 2 * tg);
            qa[ks][2] = *(const uint32_t*)(qr0 + 16 * ks + 8 + 2 * tg);
            qa[ks][3] = *(const uint32_t*)(qr1 + 16 * ks + 8 + 2 * tg);
        }
    }

    float m[2], l[2], O[16][4];
    m[0] = m[1] = -1e30f;
    l[0] = l[1] = 0.f;
#pragma unroll
    for (int nt = 0; nt < 16; nt++)
#pragma unroll
        for (int e = 0; e < 4; e++) O[nt][e] = 0.f;

    const int ntile = (q0 + FBQ) / FBKV;
    for (int i = 0; i < ntile; i++) {
        const int st = i & 1;
        const int offK = OFFW_K0 + st * KW_STG;
        const int offV = OFFW_V0 + st * VW_STG;
        const int offP = offK;

        CP_WAIT0();
        __syncthreads();

        if (i + 1 < ntile) {
            const int k0n = (i + 1) * FBKV;
            const int offKn = OFFW_K0 + (st ^ 1) * KW_STG;
            const int offVn = OFFW_V0 + (st ^ 1) * VW_STG;
#pragma unroll
            for (int j = 0; j < 8; j++) {
                const int f = tid + j * 128;
                const int rk = f >> 4, ckw = (f & 15) * 4;
                cpa16(fsb + (uint32_t)(offKn + rk * KW_S + ckw) * 4,
                      kbase + (size_t)(k0n + rk) * HKVn * Dh + ckw * 2);
                const int rv = f >> 3, cvw = (f & 7) * 4;
                cpa16(fsb + (uint32_t)(offVn + rv * VW_S + cvw) * 4,
                      vbase + (size_t)rv * Sq + k0n + cvw * 2);
            }
        }
        CP_COMMIT();

        float sc[8][4];
#pragma unroll
        for (int nt = 0; nt < 8; nt++)
#pragma unroll
            for (int e = 0; e < 4; e++) sc[nt][e] = 0.f;

#pragma unroll
        for (int ks = 0; ks < 8; ks++) {
            const int kb = ks * 8;
#pragma unroll
            for (int nt = 0; nt < 8; nt++) {
                const uint32_t* pk = &fsw[offK + (nt * 8 + g) * KW_S + kb + tg];
                uint32_t bb[2] = {pk[0], pk[4]};
                mma_f16(sc[nt], qa[ks], bb);
            }
        }

        const int k0 = i * FBKV;
        if (k0 + FBKV - 1 > q0) {
#pragma unroll
            for (int nt = 0; nt < 8; nt++)
#pragma unroll
                for (int e = 0; e < 4; e++) {
                    const int qg = q0 + wband + g + ((e >> 1) << 3);
                    const int kg = k0 + nt * 8 + tg * 2 + (e & 1);
                    if (kg > qg) sc[nt][e] = -1e30f;
                }
        }

        __syncthreads();

        float corr[2];
#pragma unroll
        for (int r2 = 0; r2 < 2; r2++) {
            float tm = -1e30f;
#pragma unroll
            for (int nt = 0; nt < 8; nt++)
                tm = fmaxf(tm, fmaxf(sc[nt][r2 * 2], sc[nt][r2 * 2 + 1]));
            tm = fmaxf(tm, __shfl_xor_sync(0xffffffffu, tm, 1));
            tm = fmaxf(tm, __shfl_xor_sync(0xffffffffu, tm, 2));
            const float mn = fmaxf(m[r2], tm);
            corr[r2] = exp2f(m[r2] - mn);
            m[r2] = mn;
            float s2 = 0.f;
            const int prow = offP + (wband + g + r2 * 8) * VW_S;
#pragma unroll
            for (int nt = 0; nt < 8; nt++) {
                float p0 = exp2f(sc[nt][r2 * 2]     - mn);
                float p1 = exp2f(sc[nt][r2 * 2 + 1] - mn);
                __half2 hp = __floats2half2_rn(p0, p1);
                float2 pr = __half22float2(hp);
                s2 += pr.x + pr.y;
                fsw[prow + nt * 4 + tg] = *(uint32_t*)&hp;
            }
            s2 += __shfl_xor_sync(0xffffffffu, s2, 1);
            s2 += __shfl_xor_sync(0xffffffffu, s2, 2);
            l[r2] = l[r2] * corr[r2] + s2;
        }

#pragma unroll
        for (int nt = 0; nt < 16; nt++) {
            O[nt][0] *= corr[0]; O[nt][1] *= corr[0];
            O[nt][2] *= corr[1]; O[nt][3] *= corr[1];
        }
        __syncwarp();

#pragma unroll
        for (int ks = 0; ks < 4; ks++) {
            const int kb = ks * 8;
            uint32_t a[4];
            {
                const uint32_t* p = &fsw[offP + (wband + g) * VW_S + kb + tg];
                a[0] = p[0];
                a[1] = p[8 * VW_S];
                a[2] = p[4];
                a[3] = p[8 * VW_S + 4];
            }
#pragma unroll
            for (int nt = 0; nt < 16; nt++) {
                const uint32_t* pv = &fsw[offV + (nt * 8 + g) * VW_S + kb + tg];
                uint32_t bb[2] = {pv[0], pv[4]};
                mma_f16(O[nt], a, bb);
            }
        }
    }

    const float inv0 = 1.f / l[0];
    const float inv1 = 1.f / l[1];
    const int row0 = q0 + wband + g;
    __half* base0 = ctx + (((size_t)b * Sq + row0) * HQn + h) * Dh;
    __half* base1 = base0 + (size_t)8 * HQn * Dh;
#pragma unroll
    for (int nt = 0; nt < 16; nt++) {
        const int col = nt * 8 + tg * 2;
        *(__half2*)&base0[col] = __floats2half2_rn(O[nt][0] * inv0,
                                                   O[nt][1] * inv0);
        *(__half2*)&base1[col] = __floats2half2_rn(O[nt][2] * inv1,
                                                   O[nt][3] * inv1);
    }
}

// ---------------------------------------------------------------------------
// Launch
// ---------------------------------------------------------------------------
extern "C" void kernel_launch(void* const* d_in, const int* in_sizes, int n_in,
                              void* d_out, int out_size) {
    const float* hidden = (const float*)d_in[0];
    const float* cosb   = (const float*)d_in[1];
    const float* sinb   = (const float*)d_in[2];
    const float* Wq = (const float*)d_in[4];
    const float* Wk = (const float*)d_in[5];
    const float* Wv = (const float*)d_in[6];
    const float* Wo = (const float*)d_in[7];
    const float* qw = (const float*)d_in[8];
    const float* kw = (const float*)d_in[9];
    float* out = (float*)d_out;

    __half *qb, *kb, *vb, *cb, *hidH, *wqkvT, *woT, *vtb;
    cudaGetSymbolAddress((void**)&qb, g_qH);
    cudaGetSymbolAddress((void**)&kb, g_kH);
    cudaGetSymbolAddress((void**)&vb, g_vH);
    cudaGetSymbolAddress((void**)&cb, g_ctxH);
    cudaGetSymbolAddress((void**)&hidH, g_hidH);
    cudaGetSymbolAddress((void**)&wqkvT, g_WqkvT);
    cudaGetSymbolAddress((void**)&woT, g_WoT);
    cudaGetSymbolAddress((void**)&vtb, g_vT);

    // q scale = 1/sqrt(128) * log2(e)  (exp2-domain softmax)
    const float qscale = 0.088388347648318447f * 1.4426950408889634f;
    const int NPERS = 296;                      // 148 SMs x occupancy 2

    // Fused prep: hidden cvt + all weight transposes
    prep_kernel<<<CVT_BLOCKS + TR_BLOCKS, 256>>>(
        hidden, hidH, Wq, Wk, Wv, Wo, wqkvT, woT);

    cudaFuncSetAttribute((const void*)gemm_f16<1, __half>,
                         cudaFuncAttributeMaxDynamicSharedMemorySize, GEMM_SMEM);
    cudaFuncSetAttribute((const void*)gemm_f16<0, float>,
                         cudaFuncAttributeMaxDynamicSharedMemorySize, GEMM_SMEM);

    // Fused QKV projection (persistent; 128x64 tiles: 32 x 48 = 1536 tiles)
    gemm_f16<1, __half><<<NPERS, 256, GEMM_SMEM>>>(
        hidH, wqkvT, Hd, 1536, 48, qb, kb, vb);

    // RMSNorm+RoPE (q,k) + V transpose
    postqkv_kernel<<<NORM_BLOCKS + VT_BLOCKS, 256>>>(
        qb, kb, vb, vtb, qw, kw, cosb, sinb, qscale);

    // Flash attention (1D LPT grid)
    cudaFuncSetAttribute(flash_mma_kernel,
                         cudaFuncAttributeMaxDynamicSharedMemorySize, FLASH_SMEM);
    flash_mma_kernel<<<(Sq / FBQ) * Bq * HQn, 128, FLASH_SMEM>>>(
        qb, kb, vtb, cb);

    // Output projection (persistent; 128x64 tiles: 32 x 32 = 1024 tiles)
    gemm_f16<0, float><<<NPERS, 256, GEMM_SMEM>>>(
        cb, woT, HQn * Dh, 1024, 32, out, nullptr, nullptr);
}

// round 16
// speedup vs baseline: 1.1330x; 1.1330x over previous
#include <cuda_runtime.h>
#include <cuda_fp16.h>
#include <cstdint>

// Problem constants (fixed by the dataset)
#define Bq   2
#define Sq   2048
#define Hd   2048
#define HQn  16
#define HKVn 4
#define Dh   128
#define NREP (HQn / HKVn)

// Scratch (device globals; no runtime allocation allowed) — fp16 dataflow
__device__ __half g_qH[(size_t)Bq * Sq * HQn * Dh];     // 16 MB
__device__ __half g_kH[(size_t)Bq * Sq * HKVn * Dh];    // 4 MB
__device__ __half g_vH[(size_t)Bq * Sq * HKVn * Dh];    // 4 MB
__device__ __half g_ctxH[(size_t)Bq * Sq * HQn * Dh];   // 16 MB
__device__ __half g_hidH[(size_t)Bq * Sq * Hd];         // 16 MB
__device__ __half g_WqkvT[(size_t)3072 * 2048];         // 12 MB
__device__ __half g_WoT[(size_t)2048 * 2048];           // 8 MB
__device__ __half g_vT[(size_t)Bq * HKVn * Dh * Sq];    // 4 MB

// ---------------------------------------------------------------------------
// Helpers
// ---------------------------------------------------------------------------
__device__ __forceinline__ uint32_t smem_to_u32(const void* p) {
    uint32_t a;
    asm("{ .reg .u64 t; cvta.to.shared.u64 t, %1; cvt.u32.u64 %0, t; }"
        : "=r"(a) : "l"(p));
    return a;
}

__device__ __forceinline__ void mma_f16(float* d, const uint32_t* a,
                                        const uint32_t* b) {
    asm volatile(
        "mma.sync.aligned.m16n8k16.row.col.f32.f16.f16.f32 "
        "{%0,%1,%2,%3}, {%4,%5,%6,%7}, {%8,%9}, {%0,%1,%2,%3};"
        : "+f"(d[0]), "+f"(d[1]), "+f"(d[2]), "+f"(d[3])
        : "r"(a[0]), "r"(a[1]), "r"(a[2]), "r"(a[3]), "r"(b[0]), "r"(b[1]));
}

__device__ __forceinline__ void cpa16(uint32_t dst, const void* src) {
    asm volatile("cp.async.cg.shared.global [%0], [%1], 16;"
                 :: "r"(dst), "l"(src) : "memory");
}
#define CP_COMMIT() asm volatile("cp.async.commit_group;" ::: "memory")
#define CP_WAIT0()  asm volatile("cp.async.wait_group 0;" ::: "memory")
#define CP_WAIT1()  asm volatile("cp.async.wait_group 1;" ::: "memory")

// ---------------------------------------------------------------------------
// Fused prep, ONE launch: hidden fp32->fp16 cvt + all 4 weight transposes.
// Transpose uses 64-row tiles (L2-merged 128 B output segments).
// ---------------------------------------------------------------------------
#define CVT_N4     (Bq * Sq * Hd / 4)          // 2097152
#define CVT_BLOCKS (CVT_N4 / 256)              // 8192
#define TRB_PER_W  2048
#define TR_BLOCKS  (4 * TRB_PER_W)             // 8192

__global__ void prep_kernel(const float* __restrict__ hidden,
                            __half* __restrict__ hidH,
                            const float* __restrict__ Wq,
                            const float* __restrict__ Wk,
                            const float* __restrict__ Wv,
                            const float* __restrict__ Wo,
                            __half* __restrict__ wqkvT,
                            __half* __restrict__ woT) {
    if (blockIdx.x < CVT_BLOCKS) {
        const int i = blockIdx.x * 256 + threadIdx.x;
        float4 x = ((const float4*)hidden)[i];
        ((__half2*)hidH)[2 * i]     = __floats2half2_rn(x.x, x.y);
        ((__half2*)hidH)[2 * i + 1] = __floats2half2_rn(x.z, x.w);
        return;
    }
    const int bid = blockIdx.x - CVT_BLOCKS;
    const int z = bid / TRB_PER_W;
    const float* in;
    __half* out;
    int C;
    if (z == 0)      { in = Wq; out = wqkvT;                       C = 2048; }
    else if (z == 1) { in = Wk; out = wqkvT + (size_t)2048 * 2048; C = 512; }
    else if (z == 2) { in = Wv; out = wqkvT + (size_t)2560 * 2048; C = 512; }
    else             { in = Wo; out = woT;                         C = 2048; }
    const int lb = bid % TRB_PER_W;
    const int bx = (lb & 63) * 32;
    const int by = (lb >> 6) * 64;
    if (bx >= C) return;

    __shared__ float t[64][33];
    const int x = threadIdx.x & 31, y = threadIdx.x >> 5;
#pragma unroll
    for (int j = 0; j < 64; j += 8)
        t[y + j][x] = in[(size_t)(by + y + j) * C + bx + x];
    __syncthreads();
#pragma unroll
    for (int jj = 0; jj < 4; jj++) {
        const int oc = y * 4 + jj;
        __half* orow = out + (size_t)(bx + oc) * 2048 + by;
        orow[x]      = __float2half(t[x][oc]);
        orow[32 + x] = __float2half(t[32 + x][oc]);
    }
}

// ---------------------------------------------------------------------------
// PERSISTENT FP16 m16n8k16 GEMM, cp.async 3-stage pipeline.
// CTA tile 128x128 (round-14 proven config; 128x64 regressed in round 15).
// ---------------------------------------------------------------------------
#define NST  3
#define STW  2560
#define GEMM_SMEM (NST * STW * 2 * 4)          // 61440 B

template <int QKV, typename CT>
__global__ void __launch_bounds__(256, 2)
gemm_f16(const __half* __restrict__ A, const __half* __restrict__ Bt, int K,
         int ntiles, int nx,
         CT* __restrict__ C0, CT* __restrict__ C1, CT* __restrict__ C2) {
    extern __shared__ uint32_t smw[];
    const uint32_t smu = smem_to_u32(smw);

    const int tid = threadIdx.x;
    const int lane = tid & 31, wid = tid >> 5;
    const int wm = (wid & 1) * 64, wn = (wid >> 1) * 32;
    const int g = lane >> 2, tg = lane & 3;

    const int rowj[2] = {tid >> 2, (tid + 256) >> 2};
    const int c8 = (tid & 3) * 8;

    const uint32_t stB = STW * 4;
    uint32_t dA[2], dB[2];
#pragma unroll
    for (int j = 0; j < 2; j++) {
        dA[j] = smu + (uint32_t)(rowj[j] * 20 + c8 / 2) * 4;
        dB[j] = dA[j] + NST * stB;
    }

    const int nk = K / 32;

    for (int t = blockIdx.x; t < ntiles; t += gridDim.x) {
        const int m0 = (t / nx) * 128, n0 = (t % nx) * 128;
        const __half* Ab = A + (size_t)m0 * K;
        const __half* Bb = Bt + (size_t)n0 * K;

        CP_WAIT0();
        __syncthreads();

#pragma unroll
        for (int p = 0; p < NST - 1; p++) {
            const size_t kk = (size_t)p * 32 + c8;
#pragma unroll
            for (int j = 0; j < 2; j++) {
                cpa16(dA[j] + p * stB, Ab + (size_t)rowj[j] * K + kk);
                cpa16(dB[j] + p * stB, Bb + (size_t)rowj[j] * K + kk);
            }
            CP_COMMIT();
        }

        float acc[4][4][4];
#pragma unroll
        for (int mi = 0; mi < 4; mi++)
#pragma unroll
            for (int ni = 0; ni < 4; ni++)
#pragma unroll
                for (int e = 0; e < 4; e++) acc[mi][ni][e] = 0.f;

        for (int kt = 0; kt < nk; kt++) {
            CP_WAIT1();
            __syncthreads();

            const int kf = kt + NST - 1;
            if (kf < nk) {
                const int s = kf % NST;
                const size_t kk = (size_t)kf * 32 + c8;
#pragma unroll
                for (int j = 0; j < 2; j++) {
                    cpa16(dA[j] + s * stB, Ab + (size_t)rowj[j] * K + kk);
                    cpa16(dB[j] + s * stB, Bb + (size_t)rowj[j] * K + kk);
                }
            }
            CP_COMMIT();

            const uint32_t* aw = smw + (kt % NST) * STW;
            const uint32_t* bw = smw + NST * STW + (kt % NST) * STW;
#pragma unroll
            for (int ks = 0; ks < 2; ks++) {
                const int kb = ks * 8;
                uint32_t af[4][4], bf[4][2];
#pragma unroll
                for (int mi = 0; mi < 4; mi++) {
                    const uint32_t* p = &aw[(wm + mi * 16 + g) * 20 + kb + tg];
                    af[mi][0] = p[0];
                    af[mi][1] = p[8 * 20];
                    af[mi][2] = p[4];
                    af[mi][3] = p[8 * 20 + 4];
                }
#pragma unroll
                for (int ni = 0; ni < 4; ni++) {
                    const uint32_t* p = &bw[(wn + ni * 8 + g) * 20 + kb + tg];
                    bf[ni][0] = p[0];
                    bf[ni][1] = p[4];
                }
#pragma unroll
                for (int mi = 0; mi < 4; mi++)
#pragma unroll
                    for (int ni = 0; ni < 4; ni++)
                        mma_f16(acc[mi][ni], af[mi], bf[ni]);
            }
        }

        CT* C;
        int ldc, col0;
        if (QKV) {
            if (n0 < 2048)      { C = C0; ldc = 2048; col0 = n0; }
            else if (n0 < 2560) { C = C1; ldc = 512;  col0 = n0 - 2048; }
            else                { C = C2; ldc = 512;  col0 = n0 - 2560; }
        } else {
            C = C0; ldc = 2048; col0 = n0;
        }
#pragma unroll
        for (int mi = 0; mi < 4; mi++) {
            const int row0 = m0 + wm + mi * 16 + g;
#pragma unroll
            for (int ni = 0; ni < 4; ni++) {
                const int col = col0 + wn + ni * 8 + tg * 2;
                if constexpr (sizeof(CT) == 2) {
                    *(__half2*)&C[(size_t)row0 * ldc + col] =
                        __floats2half2_rn(acc[mi][ni][0], acc[mi][ni][1]);
                    *(__half2*)&C[(size_t)(row0 + 8) * ldc + col] =
                        __floats2half2_rn(acc[mi][ni][2], acc[mi][ni][3]);
                } else {
                    *(float2*)&C[(size_t)row0 * ldc + col] =
                        make_float2(acc[mi][ni][0], acc[mi][ni][1]);
                    *(float2*)&C[(size_t)(row0 + 8) * ldc + col] =
                        make_float2(acc[mi][ni][2], acc[mi][ni][3]);
                }
            }
        }
    }
}

// ---------------------------------------------------------------------------
// Post-QKV fixup, ONE launch: RMSNorm+RoPE (q scaled by scale*log2(e) for
// exp2-domain softmax) and V transpose.
// ---------------------------------------------------------------------------
#define NQROWS (Bq * Sq * HQn)
#define NKROWS (Bq * Sq * HKVn)
#define NORM_BLOCKS ((NQROWS + NKROWS) / 8)
#define VT_BLOCKS   (4 * 64 * Bq * HKVn)

__global__ void postqkv_kernel(__half* __restrict__ qx,
                               __half* __restrict__ kx,
                               const __half* __restrict__ v,
                               __half* __restrict__ vt,
                               const float* __restrict__ qw,
                               const float* __restrict__ kw,
                               const float* __restrict__ cosb,
                               const float* __restrict__ sinb,
                               float qscale) {
    if (blockIdx.x < NORM_BLOCKS) {
        const int row = blockIdx.x * 8 + (threadIdx.x >> 5);
        const int l   = threadIdx.x & 31;

        __half* x;
        const float* w;
        float scale;
        int r, nheads;
        if (row < NQROWS) { x = qx; w = qw; scale = qscale; r = row; nheads = HQn; }
        else              { x = kx; w = kw; scale = 1.0f;  r = row - NQROWS; nheads = HKVn; }
        const int s = (r / nheads) % Sq;

        __half2* rp = (__half2*)(x + (size_t)r * Dh);
        float2 a = __half22float2(rp[l]);
        float2 b = __half22float2(rp[l + 32]);

        float ss = a.x * a.x + a.y * a.y + b.x * b.x + b.y * b.y;
#pragma unroll
        for (int off = 16; off > 0; off >>= 1)
            ss += __shfl_xor_sync(0xffffffffu, ss, off);
        const float rinv = rsqrtf(ss * (1.0f / Dh) + 1e-6f);

        const float2 wa = *(const float2*)&w[2 * l];
        const float2 wb = *(const float2*)&w[64 + 2 * l];
        const float xa0 = a.x * rinv * wa.x, xa1 = a.y * rinv * wa.y;
        const float xb0 = b.x * rinv * wb.x, xb1 = b.y * rinv * wb.y;

        const float* cb = cosb + (size_t)s * Dh;
        const float* sb = sinb + (size_t)s * Dh;
        const float2 ca = *(const float2*)&cb[2 * l];
        const float2 cb2 = *(const float2*)&cb[64 + 2 * l];
        const float2 sa = *(const float2*)&sb[2 * l];
        const float2 sb2 = *(const float2*)&sb[64 + 2 * l];

        const float oa0 = (xa0 * ca.x - xb0 * sa.x) * scale;
        const float oa1 = (xa1 * ca.y - xb1 * sa.y) * scale;
        const float ob0 = (xb0 * cb2.x + xa0 * sb2.x) * scale;
        const float ob1 = (xb1 * cb2.y + xa1 * sb2.y) * scale;

        rp[l]      = __floats2half2_rn(oa0, oa1);
        rp[l + 32] = __floats2half2_rn(ob0, ob1);
    } else {
        const int bid = blockIdx.x - NORM_BLOCKS;
        const int d0 = (bid & 3) * 32;
        const int s0 = ((bid >> 2) & 63) * 32;
        const int z  = bid >> 8;
        const int b = z >> 2, hkv = z & 3;
        const int x = threadIdx.x & 31, y = threadIdx.x >> 5;

        __shared__ __half t[32][34];
        const __half* src = v + (size_t)b * Sq * 512 + hkv * 128;
#pragma unroll
        for (int j = 0; j < 32; j += 8)
            t[y + j][x] = src[(size_t)(s0 + y + j) * 512 + d0 + x];
        __syncthreads();
        __half* dst = vt + ((size_t)z * 128 + d0) * Sq + s0;
#pragma unroll
        for (int j = 0; j < 32; j += 8)
            dst[(size_t)(y + j) * Sq + x] = t[x][y + j];
    }
}

// ---------------------------------------------------------------------------
// Flash attention (round-14 exact: Q-regs, P-alias, exp2 softmax, LPT grid).
// ---------------------------------------------------------------------------
#define FBQ   64
#define FBKV  64
#define KW_S  68
#define VW_S  36
#define OFFW_K0 0
#define KW_STG  (FBKV * KW_S)          // 4352 words
#define OFFW_V0 (2 * KW_STG)           // 8704
#define VW_STG  (Dh * VW_S)            // 4608
#define FLASH_SMEM ((OFFW_V0 + 2 * VW_STG) * 4)   // 71680 B

__global__ void __launch_bounds__(128, 3)
flash_mma_kernel(const __half* __restrict__ q,
                 const __half* __restrict__ k,
                 const __half* __restrict__ vt,
                 __half* __restrict__ ctx) {
    extern __shared__ uint32_t fsw[];
    const uint32_t fsb = smem_to_u32(fsw);

    const int bid = blockIdx.x;
    const int bh  = bid & 31;
    const int q0  = (31 - (bid >> 5)) * FBQ;
    const int b   = bh / HQn;
    const int h   = bh % HQn;
    const int hkv = h / NREP;

    const int tid  = threadIdx.x;
    const int lane = tid & 31, wid = tid >> 5;
    const int g = lane >> 2, tg = lane & 3;
    const int wband = wid * 16;

    const __half* kbase = k + ((size_t)b * Sq * HKVn + hkv) * Dh;
    const __half* vbase = vt + (size_t)(b * HKVn + hkv) * Dh * Sq;

#pragma unroll
    for (int j = 0; j < 8; j++) {
        const int f = tid + j * 128;
        const int rk = f >> 4, ckw = (f & 15) * 4;
        cpa16(fsb + (uint32_t)(OFFW_K0 + rk * KW_S + ckw) * 4,
              kbase + (size_t)rk * HKVn * Dh + ckw * 2);
        const int rv = f >> 3, cvw = (f & 7) * 4;
        cpa16(fsb + (uint32_t)(OFFW_V0 + rv * VW_S + cvw) * 4,
              vbase + (size_t)rv * Sq + cvw * 2);
    }
    CP_COMMIT();

    uint32_t qa[8][4];
    {
        const __half* qr0 = q + (((size_t)b * Sq + q0 + wband + g) * HQn + h) * Dh;
        const __half* qr1 = qr0 + (size_t)8 * HQn * Dh;
#pragma unroll
        for (int ks = 0; ks < 8; ks++) {
            qa[ks][0] = *(const uint32_t*)(qr0 + 16 * ks + 2 * tg);
            qa[ks][1] = *(const uint32_t*)(qr1 + 16 * ks + 2 * tg);
            qa[ks][2] = *(const uint32_t*)(qr0 + 16 * ks + 8 + 2 * tg);
            qa[ks][3] = *(const uint32_t*)(qr1 + 16 * ks + 8 + 2 * tg);
        }
    }

    float m[2], l[2], O[16][4];
    m[0] = m[1] = -1e30f;
    l[0] = l[1] = 0.f;
#pragma unroll
    for (int nt = 0; nt < 16; nt++)
#pragma unroll
        for (int e = 0; e < 4; e++) O[nt][e] = 0.f;

    const int ntile = (q0 + FBQ) / FBKV;
    for (int i = 0; i < ntile; i++) {
        const int st = i & 1;
        const int offK = OFFW_K0 + st * KW_STG;
        const int offV = OFFW_V0 + st * VW_STG;
        const int offP = offK;

        CP_WAIT0();
        __syncthreads();

        if (i + 1 < ntile) {
            const int k0n = (i + 1) * FBKV;
            const int offKn = OFFW_K0 + (st ^ 1) * KW_STG;
            const int offVn = OFFW_V0 + (st ^ 1) * VW_STG;
#pragma unroll
            for (int j = 0; j < 8; j++) {
                const int f = tid + j * 128;
                const int rk = f >> 4, ckw = (f & 15) * 4;
                cpa16(fsb + (uint32_t)(offKn + rk * KW_S + ckw) * 4,
                      kbase + (size_t)(k0n + rk) * HKVn * Dh + ckw * 2);
                const int rv = f >> 3, cvw = (f & 7) * 4;
                cpa16(fsb + (uint32_t)(offVn + rv * VW_S + cvw) * 4,
                      vbase + (size_t)rv * Sq + k0n + cvw * 2);
            }
        }
        CP_COMMIT();

        float sc[8][4];
#pragma unroll
        for (int nt = 0; nt < 8; nt++)
#pragma unroll
            for (int e = 0; e < 4; e++) sc[nt][e] = 0.f;

#pragma unroll
        for (int ks = 0; ks < 8; ks++) {
            const int kb = ks * 8;
#pragma unroll
            for (int nt = 0; nt < 8; nt++) {
                const uint32_t* pk = &fsw[offK + (nt * 8 + g) * KW_S + kb + tg];
                uint32_t bb[2] = {pk[0], pk[4]};
                mma_f16(sc[nt], qa[ks], bb);
            }
        }

        const int k0 = i * FBKV;
        if (k0 + FBKV - 1 > q0) {
#pragma unroll
            for (int nt = 0; nt < 8; nt++)
#pragma unroll
                for (int e = 0; e < 4; e++) {
                    const int qg = q0 + wband + g + ((e >> 1) << 3);
                    const int kg = k0 + nt * 8 + tg * 2 + (e & 1);
                    if (kg > qg) sc[nt][e] = -1e30f;
                }
        }

        __syncthreads();

        float corr[2];
#pragma unroll
        for (int r2 = 0; r2 < 2; r2++) {
            float tm = -1e30f;
#pragma unroll
            for (int nt = 0; nt < 8; nt++)
                tm = fmaxf(tm, fmaxf(sc[nt][r2 * 2], sc[nt][r2 * 2 + 1]));
            tm = fmaxf(tm, __shfl_xor_sync(0xffffffffu, tm, 1));
            tm = fmaxf(tm, __shfl_xor_sync(0xffffffffu, tm, 2));
            const float mn = fmaxf(m[r2], tm);
            corr[r2] = exp2f(m[r2] - mn);
            m[r2] = mn;
            float s2 = 0.f;
            const int prow = offP + (wband + g + r2 * 8) * VW_S;
#pragma unroll
            for (int nt = 0; nt < 8; nt++) {
                float p0 = exp2f(sc[nt][r2 * 2]     - mn);
                float p1 = exp2f(sc[nt][r2 * 2 + 1] - mn);
                __half2 hp = __floats2half2_rn(p0, p1);
                float2 pr = __half22float2(hp);
                s2 += pr.x + pr.y;
                fsw[prow + nt * 4 + tg] = *(uint32_t*)&hp;
            }
            s2 += __shfl_xor_sync(0xffffffffu, s2, 1);
            s2 += __shfl_xor_sync(0xffffffffu, s2, 2);
            l[r2] = l[r2] * corr[r2] + s2;
        }

#pragma unroll
        for (int nt = 0; nt < 16; nt++) {
            O[nt][0] *= corr[0]; O[nt][1] *= corr[0];
            O[nt][2] *= corr[1]; O[nt][3] *= corr[1];
        }
        __syncwarp();

#pragma unroll
        for (int ks = 0; ks < 4; ks++) {
            const int kb = ks * 8;
            uint32_t a[4];
            {
                const uint32_t* p = &fsw[offP + (wband + g) * VW_S + kb + tg];
                a[0] = p[0];
                a[1] = p[8 * VW_S];
                a[2] = p[4];
                a[3] = p[8 * VW_S + 4];
            }
#pragma unroll
            for (int nt = 0; nt < 16; nt++) {
                const uint32_t* pv = &fsw[offV + (nt * 8 + g) * VW_S + kb + tg];
                uint32_t bb[2] = {pv[0], pv[4]};
                mma_f16(O[nt], a, bb);
            }
        }
    }

    const float inv0 = 1.f / l[0];
    const float inv1 = 1.f / l[1];
    const int row0 = q0 + wband + g;
    __half* base0 = ctx + (((size_t)b * Sq + row0) * HQn + h) * Dh;
    __half* base1 = base0 + (size_t)8 * HQn * Dh;
#pragma unroll
    for (int nt = 0; nt < 16; nt++) {
        const int col = nt * 8 + tg * 2;
        *(__half2*)&base0[col] = __floats2half2_rn(O[nt][0] * inv0,
                                                   O[nt][1] * inv0);
        *(__half2*)&base1[col] = __floats2half2_rn(O[nt][2] * inv1,
                                                   O[nt][3] * inv1);
    }
}

// ---------------------------------------------------------------------------
// Launch
// ---------------------------------------------------------------------------
extern "C" void kernel_launch(void* const* d_in, const int* in_sizes, int n_in,
                              void* d_out, int out_size) {
    const float* hidden = (const float*)d_in[0];
    const float* cosb   = (const float*)d_in[1];
    const float* sinb   = (const float*)d_in[2];
    const float* Wq = (const float*)d_in[4];
    const float* Wk = (const float*)d_in[5];
    const float* Wv = (const float*)d_in[6];
    const float* Wo = (const float*)d_in[7];
    const float* qw = (const float*)d_in[8];
    const float* kw = (const float*)d_in[9];
    float* out = (float*)d_out;

    __half *qb, *kb, *vb, *cb, *hidH, *wqkvT, *woT, *vtb;
    cudaGetSymbolAddress((void**)&qb, g_qH);
    cudaGetSymbolAddress((void**)&kb, g_kH);
    cudaGetSymbolAddress((void**)&vb, g_vH);
    cudaGetSymbolAddress((void**)&cb, g_ctxH);
    cudaGetSymbolAddress((void**)&hidH, g_hidH);
    cudaGetSymbolAddress((void**)&wqkvT, g_WqkvT);
    cudaGetSymbolAddress((void**)&woT, g_WoT);
    cudaGetSymbolAddress((void**)&vtb, g_vT);

    // q scale = 1/sqrt(128) * log2(e)  (exp2-domain softmax)
    const float qscale = 0.088388347648318447f * 1.4426950408889634f;
    const int NPERS = 296;                      // 148 SMs x occupancy 2

    // Fused prep: hidden cvt + all weight transposes
    prep_kernel<<<CVT_BLOCKS + TR_BLOCKS, 256>>>(
        hidden, hidH, Wq, Wk, Wv, Wo, wqkvT, woT);

    cudaFuncSetAttribute((const void*)gemm_f16<1, __half>,
                         cudaFuncAttributeMaxDynamicSharedMemorySize, GEMM_SMEM);
    cudaFuncSetAttribute((const void*)gemm_f16<0, float>,
                         cudaFuncAttributeMaxDynamicSharedMemorySize, GEMM_SMEM);

    // Fused QKV projection (persistent; 128x128 tiles: 768 over 296 CTAs)
    gemm_f16<1, __half><<<NPERS, 256, GEMM_SMEM>>>(
        hidH, wqkvT, Hd, 768, 24, qb, kb, vb);

    // RMSNorm+RoPE (q,k) + V transpose
    postqkv_kernel<<<NORM_BLOCKS + VT_BLOCKS, 256>>>(
        qb, kb, vb, vtb, qw, kw, cosb, sinb, qscale);

    // Flash attention (1D LPT grid)
    cudaFuncSetAttribute(flash_mma_kernel,
                         cudaFuncAttributeMaxDynamicSharedMemorySize, FLASH_SMEM);
    flash_mma_kernel<<<(Sq / FBQ) * Bq * HQn, 128, FLASH_SMEM>>>(
        qb, kb, vtb, cb);

    // Output projection (persistent; 128x128 tiles: 512 over 296 CTAs)
    gemm_f16<0, float><<<NPERS, 256, GEMM_SMEM>>>(
        cb, woT, HQn * Dh, 512, 16, out, nullptr, nullptr);
}

// round 17
// speedup vs baseline: 1.1365x; 1.0031x over previous
#include <cuda_runtime.h>
#include <cuda_fp16.h>
#include <cstdint>

// Problem constants (fixed by the dataset)
#define Bq   2
#define Sq   2048
#define Hd   2048
#define HQn  16
#define HKVn 4
#define Dh   128
#define NREP (HQn / HKVn)

// Scratch (device globals; no runtime allocation allowed) — fp16 dataflow
__device__ __half g_qH[(size_t)Bq * Sq * HQn * Dh];     // 16 MB
__device__ __half g_kH[(size_t)Bq * Sq * HKVn * Dh];    // 4 MB
__device__ __half g_vH[(size_t)Bq * Sq * HKVn * Dh];    // 4 MB
__device__ __half g_ctxH[(size_t)Bq * Sq * HQn * Dh];   // 16 MB
__device__ __half g_hidH[(size_t)Bq * Sq * Hd];         // 16 MB
__device__ __half g_WqkvT[(size_t)3072 * 2048];         // 12 MB
__device__ __half g_WoT[(size_t)2048 * 2048];           // 8 MB
__device__ __half g_vT[(size_t)Bq * HKVn * Dh * Sq];    // 4 MB

// ---------------------------------------------------------------------------
// Helpers
// ---------------------------------------------------------------------------
__device__ __forceinline__ uint32_t smem_to_u32(const void* p) {
    uint32_t a;
    asm("{ .reg .u64 t; cvta.to.shared.u64 t, %1; cvt.u32.u64 %0, t; }"
        : "=r"(a) : "l"(p));
    return a;
}

__device__ __forceinline__ void mma_f16(float* d, const uint32_t* a,
                                        const uint32_t* b) {
    asm volatile(
        "mma.sync.aligned.m16n8k16.row.col.f32.f16.f16.f32 "
        "{%0,%1,%2,%3}, {%4,%5,%6,%7}, {%8,%9}, {%0,%1,%2,%3};"
        : "+f"(d[0]), "+f"(d[1]), "+f"(d[2]), "+f"(d[3])
        : "r"(a[0]), "r"(a[1]), "r"(a[2]), "r"(a[3]), "r"(b[0]), "r"(b[1]));
}

__device__ __forceinline__ void cpa16(uint32_t dst, const void* src) {
    asm volatile("cp.async.cg.shared.global [%0], [%1], 16;"
                 :: "r"(dst), "l"(src) : "memory");
}
#define CP_COMMIT() asm volatile("cp.async.commit_group;" ::: "memory")
#define CP_WAIT0()  asm volatile("cp.async.wait_group 0;" ::: "memory")
#define CP_WAIT1()  asm volatile("cp.async.wait_group 1;" ::: "memory")

// ---------------------------------------------------------------------------
// Fused prep, ONE launch, packed grid (no empty blocks):
//   [0, 4096)            hidden cvt, 2 float4 per thread
//   [4096, 6144)         Wq transpose (2048 blocks)
//   [6144, 6656)         Wk transpose (512 blocks)
//   [6656, 7168)         Wv transpose (512 blocks)
//   [7168, 9216)         Wo transpose (2048 blocks)
// ---------------------------------------------------------------------------
#define CVT_BLOCKS 4096
#define CVT_HALFN4 (CVT_BLOCKS * 256)          // 1048576
#define PREP_GRID  9216

__global__ void prep_kernel(const float* __restrict__ hidden,
                            __half* __restrict__ hidH,
                            const float* __restrict__ Wq,
                            const float* __restrict__ Wk,
                            const float* __restrict__ Wv,
                            const float* __restrict__ Wo,
                            __half* __restrict__ wqkvT,
                            __half* __restrict__ woT) {
    if (blockIdx.x < CVT_BLOCKS) {
        const int i0 = blockIdx.x * 256 + threadIdx.x;
#pragma unroll
        for (int j = 0; j < 2; j++) {
            const int i = i0 + j * CVT_HALFN4;
            float4 x = ((const float4*)hidden)[i];
            ((__half2*)hidH)[2 * i]     = __floats2half2_rn(x.x, x.y);
            ((__half2*)hidH)[2 * i + 1] = __floats2half2_rn(x.z, x.w);
        }
        return;
    }
    const int bid = blockIdx.x - CVT_BLOCKS;
    const float* in;
    __half* out;
    int C, lb;
    if (bid < 2048)      { in = Wq; out = wqkvT;                       C = 2048; lb = bid; }
    else if (bid < 2560) { in = Wk; out = wqkvT + (size_t)2048 * 2048; C = 512;  lb = bid - 2048; }
    else if (bid < 3072) { in = Wv; out = wqkvT + (size_t)2560 * 2048; C = 512;  lb = bid - 2560; }
    else                 { in = Wo; out = woT;                         C = 2048; lb = bid - 3072; }
    int bx, by;
    if (C == 2048) { bx = (lb & 63) * 32; by = (lb >> 6) * 64; }
    else           { bx = (lb & 15) * 32; by = (lb >> 4) * 64; }

    __shared__ float t[64][33];
    const int x = threadIdx.x & 31, y = threadIdx.x >> 5;
#pragma unroll
    for (int j = 0; j < 64; j += 8)
        t[y + j][x] = in[(size_t)(by + y + j) * C + bx + x];
    __syncthreads();
#pragma unroll
    for (int jj = 0; jj < 4; jj++) {
        const int oc = y * 4 + jj;
        __half* orow = out + (size_t)(bx + oc) * 2048 + by;
        orow[x]      = __float2half(t[x][oc]);
        orow[32 + x] = __float2half(t[32 + x][oc]);
    }
}

// ---------------------------------------------------------------------------
// PERSISTENT FP16 m16n8k16 GEMM, cp.async 3-stage pipeline (round-14 exact).
// ---------------------------------------------------------------------------
#define NST  3
#define STW  2560
#define GEMM_SMEM (NST * STW * 2 * 4)          // 61440 B

template <int QKV, typename CT>
__global__ void __launch_bounds__(256, 2)
gemm_f16(const __half* __restrict__ A, const __half* __restrict__ Bt, int K,
         int ntiles, int nx,
         CT* __restrict__ C0, CT* __restrict__ C1, CT* __restrict__ C2) {
    extern __shared__ uint32_t smw[];
    const uint32_t smu = smem_to_u32(smw);

    const int tid = threadIdx.x;
    const int lane = tid & 31, wid = tid >> 5;
    const int wm = (wid & 1) * 64, wn = (wid >> 1) * 32;
    const int g = lane >> 2, tg = lane & 3;

    const int rowj[2] = {tid >> 2, (tid + 256) >> 2};
    const int c8 = (tid & 3) * 8;

    const uint32_t stB = STW * 4;
    uint32_t dA[2], dB[2];
#pragma unroll
    for (int j = 0; j < 2; j++) {
        dA[j] = smu + (uint32_t)(rowj[j] * 20 + c8 / 2) * 4;
        dB[j] = dA[j] + NST * stB;
    }

    const int nk = K / 32;

    for (int t = blockIdx.x; t < ntiles; t += gridDim.x) {
        const int m0 = (t / nx) * 128, n0 = (t % nx) * 128;
        const __half* Ab = A + (size_t)m0 * K;
        const __half* Bb = Bt + (size_t)n0 * K;

        CP_WAIT0();
        __syncthreads();

#pragma unroll
        for (int p = 0; p < NST - 1; p++) {
            const size_t kk = (size_t)p * 32 + c8;
#pragma unroll
            for (int j = 0; j < 2; j++) {
                cpa16(dA[j] + p * stB, Ab + (size_t)rowj[j] * K + kk);
                cpa16(dB[j] + p * stB, Bb + (size_t)rowj[j] * K + kk);
            }
            CP_COMMIT();
        }

        float acc[4][4][4];
#pragma unroll
        for (int mi = 0; mi < 4; mi++)
#pragma unroll
            for (int ni = 0; ni < 4; ni++)
#pragma unroll
                for (int e = 0; e < 4; e++) acc[mi][ni][e] = 0.f;

        for (int kt = 0; kt < nk; kt++) {
            CP_WAIT1();
            __syncthreads();

            const int kf = kt + NST - 1;
            if (kf < nk) {
                const int s = kf % NST;
                const size_t kk = (size_t)kf * 32 + c8;
#pragma unroll
                for (int j = 0; j < 2; j++) {
                    cpa16(dA[j] + s * stB, Ab + (size_t)rowj[j] * K + kk);
                    cpa16(dB[j] + s * stB, Bb + (size_t)rowj[j] * K + kk);
                }
            }
            CP_COMMIT();

            const uint32_t* aw = smw + (kt % NST) * STW;
            const uint32_t* bw = smw + NST * STW + (kt % NST) * STW;
#pragma unroll
            for (int ks = 0; ks < 2; ks++) {
                const int kb = ks * 8;
                uint32_t af[4][4], bf[4][2];
#pragma unroll
                for (int mi = 0; mi < 4; mi++) {
                    const uint32_t* p = &aw[(wm + mi * 16 + g) * 20 + kb + tg];
                    af[mi][0] = p[0];
                    af[mi][1] = p[8 * 20];
                    af[mi][2] = p[4];
                    af[mi][3] = p[8 * 20 + 4];
                }
#pragma unroll
                for (int ni = 0; ni < 4; ni++) {
                    const uint32_t* p = &bw[(wn + ni * 8 + g) * 20 + kb + tg];
                    bf[ni][0] = p[0];
                    bf[ni][1] = p[4];
                }
#pragma unroll
                for (int mi = 0; mi < 4; mi++)
#pragma unroll
                    for (int ni = 0; ni < 4; ni++)
                        mma_f16(acc[mi][ni], af[mi], bf[ni]);
            }
        }

        CT* C;
        int ldc, col0;
        if (QKV) {
            if (n0 < 2048)      { C = C0; ldc = 2048; col0 = n0; }
            else if (n0 < 2560) { C = C1; ldc = 512;  col0 = n0 - 2048; }
            else                { C = C2; ldc = 512;  col0 = n0 - 2560; }
        } else {
            C = C0; ldc = 2048; col0 = n0;
        }
#pragma unroll
        for (int mi = 0; mi < 4; mi++) {
            const int row0 = m0 + wm + mi * 16 + g;
#pragma unroll
            for (int ni = 0; ni < 4; ni++) {
                const int col = col0 + wn + ni * 8 + tg * 2;
                if constexpr (sizeof(CT) == 2) {
                    *(__half2*)&C[(size_t)row0 * ldc + col] =
                        __floats2half2_rn(acc[mi][ni][0], acc[mi][ni][1]);
                    *(__half2*)&C[(size_t)(row0 + 8) * ldc + col] =
                        __floats2half2_rn(acc[mi][ni][2], acc[mi][ni][3]);
                } else {
                    *(float2*)&C[(size_t)row0 * ldc + col] =
                        make_float2(acc[mi][ni][0], acc[mi][ni][1]);
                    *(float2*)&C[(size_t)(row0 + 8) * ldc + col] =
                        make_float2(acc[mi][ni][2], acc[mi][ni][3]);
                }
            }
        }
    }
}

// ---------------------------------------------------------------------------
// Post-QKV fixup, ONE launch, packed grid: 4 rows per warp for RMSNorm+RoPE
// (2560 blocks) + V transpose (2048 blocks).
// ---------------------------------------------------------------------------
#define NQROWS (Bq * Sq * HQn)       // 65536
#define NKROWS (Bq * Sq * HKVn)      // 16384
#define NORM_BLOCKS ((NQROWS + NKROWS) / 32)   // 2560 (8 warps x 4 rows)
#define VT_BLOCKS   (4 * 64 * Bq * HKVn)       // 2048

__global__ void postqkv_kernel(__half* __restrict__ qx,
                               __half* __restrict__ kx,
                               const __half* __restrict__ v,
                               __half* __restrict__ vt,
                               const float* __restrict__ qw,
                               const float* __restrict__ kw,
                               const float* __restrict__ cosb,
                               const float* __restrict__ sinb,
                               float qscale) {
    if (blockIdx.x < NORM_BLOCKS) {
        const int l = threadIdx.x & 31;
        const int rbase = (blockIdx.x * 8 + (threadIdx.x >> 5)) * 4;
#pragma unroll
        for (int rr = 0; rr < 4; rr++) {
            const int row = rbase + rr;

            __half* x;
            const float* w;
            float scale;
            int r, nheads;
            if (row < NQROWS) { x = qx; w = qw; scale = qscale; r = row; nheads = HQn; }
            else              { x = kx; w = kw; scale = 1.0f;  r = row - NQROWS; nheads = HKVn; }
            const int s = (r / nheads) % Sq;

            __half2* rp = (__half2*)(x + (size_t)r * Dh);
            float2 a = __half22float2(rp[l]);
            float2 b = __half22float2(rp[l + 32]);

            float ss = a.x * a.x + a.y * a.y + b.x * b.x + b.y * b.y;
#pragma unroll
            for (int off = 16; off > 0; off >>= 1)
                ss += __shfl_xor_sync(0xffffffffu, ss, off);
            const float rinv = rsqrtf(ss * (1.0f / Dh) + 1e-6f);

            const float2 wa = *(const float2*)&w[2 * l];
            const float2 wb = *(const float2*)&w[64 + 2 * l];
            const float xa0 = a.x * rinv * wa.x, xa1 = a.y * rinv * wa.y;
            const float xb0 = b.x * rinv * wb.x, xb1 = b.y * rinv * wb.y;

            const float* cb = cosb + (size_t)s * Dh;
            const float* sb = sinb + (size_t)s * Dh;
            const float2 ca = *(const float2*)&cb[2 * l];
            const float2 cb2 = *(const float2*)&cb[64 + 2 * l];
            const float2 sa = *(const float2*)&sb[2 * l];
            const float2 sb2 = *(const float2*)&sb[64 + 2 * l];

            const float oa0 = (xa0 * ca.x - xb0 * sa.x) * scale;
            const float oa1 = (xa1 * ca.y - xb1 * sa.y) * scale;
            const float ob0 = (xb0 * cb2.x + xa0 * sb2.x) * scale;
            const float ob1 = (xb1 * cb2.y + xa1 * sb2.y) * scale;

            rp[l]      = __floats2half2_rn(oa0, oa1);
            rp[l + 32] = __floats2half2_rn(ob0, ob1);
        }
    } else {
        const int bid = blockIdx.x - NORM_BLOCKS;
        const int d0 = (bid & 3) * 32;
        const int s0 = ((bid >> 2) & 63) * 32;
        const int z  = bid >> 8;
        const int b = z >> 2, hkv = z & 3;
        const int x = threadIdx.x & 31, y = threadIdx.x >> 5;

        __shared__ __half t[32][34];
        const __half* src = v + (size_t)b * Sq * 512 + hkv * 128;
#pragma unroll
        for (int j = 0; j < 32; j += 8)
            t[y + j][x] = src[(size_t)(s0 + y + j) * 512 + d0 + x];
        __syncthreads();
        __half* dst = vt + ((size_t)z * 128 + d0) * Sq + s0;
#pragma unroll
        for (int j = 0; j < 32; j += 8)
            dst[(size_t)(y + j) * Sq + x] = t[x][y + j];
    }
}

// ---------------------------------------------------------------------------
// Flash attention (round-14 exact: Q-regs, P-alias, exp2 softmax, LPT grid).
// ---------------------------------------------------------------------------
#define FBQ   64
#define FBKV  64
#define KW_S  68
#define VW_S  36
#define OFFW_K0 0
#define KW_STG  (FBKV * KW_S)          // 4352 words
#define OFFW_V0 (2 * KW_STG)           // 8704
#define VW_STG  (Dh * VW_S)            // 4608
#define FLASH_SMEM ((OFFW_V0 + 2 * VW_STG) * 4)   // 71680 B

__global__ void __launch_bounds__(128, 3)
flash_mma_kernel(const __half* __restrict__ q,
                 const __half* __restrict__ k,
                 const __half* __restrict__ vt,
                 __half* __restrict__ ctx) {
    extern __shared__ uint32_t fsw[];
    const uint32_t fsb = smem_to_u32(fsw);

    const int bid = blockIdx.x;
    const int bh  = bid & 31;
    const int q0  = (31 - (bid >> 5)) * FBQ;
    const int b   = bh / HQn;
    const int h   = bh % HQn;
    const int hkv = h / NREP;

    const int tid  = threadIdx.x;
    const int lane = tid & 31, wid = tid >> 5;
    const int g = lane >> 2, tg = lane & 3;
    const int wband = wid * 16;

    const __half* kbase = k + ((size_t)b * Sq * HKVn + hkv) * Dh;
    const __half* vbase = vt + (size_t)(b * HKVn + hkv) * Dh * Sq;

#pragma unroll
    for (int j = 0; j < 8; j++) {
        const int f = tid + j * 128;
        const int rk = f >> 4, ckw = (f & 15) * 4;
        cpa16(fsb + (uint32_t)(OFFW_K0 + rk * KW_S + ckw) * 4,
              kbase + (size_t)rk * HKVn * Dh + ckw * 2);
        const int rv = f >> 3, cvw = (f & 7) * 4;
        cpa16(fsb + (uint32_t)(OFFW_V0 + rv * VW_S + cvw) * 4,
              vbase + (size_t)rv * Sq + cvw * 2);
    }
    CP_COMMIT();

    uint32_t qa[8][4];
    {
        const __half* qr0 = q + (((size_t)b * Sq + q0 + wband + g) * HQn + h) * Dh;
        const __half* qr1 = qr0 + (size_t)8 * HQn * Dh;
#pragma unroll
        for (int ks = 0; ks < 8; ks++) {
            qa[ks][0] = *(const uint32_t*)(qr0 + 16 * ks + 2 * tg);
            qa[ks][1] = *(const uint32_t*)(qr1 + 16 * ks + 2 * tg);
            qa[ks][2] = *(const uint32_t*)(qr0 + 16 * ks + 8 + 2 * tg);
            qa[ks][3] = *(const uint32_t*)(qr1 + 16 * ks + 8 + 2 * tg);
        }
    }

    float m[2], l[2], O[16][4];
    m[0] = m[1] = -1e30f;
    l[0] = l[1] = 0.f;
#pragma unroll
    for (int nt = 0; nt < 16; nt++)
#pragma unroll
        for (int e = 0; e < 4; e++) O[nt][e] = 0.f;

    const int ntile = (q0 + FBQ) / FBKV;
    for (int i = 0; i < ntile; i++) {
        const int st = i & 1;
        const int offK = OFFW_K0 + st * KW_STG;
        const int offV = OFFW_V0 + st * VW_STG;
        const int offP = offK;

        CP_WAIT0();
        __syncthreads();

        if (i + 1 < ntile) {
            const int k0n = (i + 1) * FBKV;
            const int offKn = OFFW_K0 + (st ^ 1) * KW_STG;
            const int offVn = OFFW_V0 + (st ^ 1) * VW_STG;
#pragma unroll
            for (int j = 0; j < 8; j++) {
                const int f = tid + j * 128;
                const int rk = f >> 4, ckw = (f & 15) * 4;
                cpa16(fsb + (uint32_t)(offKn + rk * KW_S + ckw) * 4,
                      kbase + (size_t)(k0n + rk) * HKVn * Dh + ckw * 2);
                const int rv = f >> 3, cvw = (f & 7) * 4;
                cpa16(fsb + (uint32_t)(offVn + rv * VW_S + cvw) * 4,
                      vbase + (size_t)rv * Sq + k0n + cvw * 2);
            }
        }
        CP_COMMIT();

        float sc[8][4];
#pragma unroll
        for (int nt = 0; nt < 8; nt++)
#pragma unroll
            for (int e = 0; e < 4; e++) sc[nt][e] = 0.f;

#pragma unroll
        for (int ks = 0; ks < 8; ks++) {
            const int kb = ks * 8;
#pragma unroll
            for (int nt = 0; nt < 8; nt++) {
                const uint32_t* pk = &fsw[offK + (nt * 8 + g) * KW_S + kb + tg];
                uint32_t bb[2] = {pk[0], pk[4]};
                mma_f16(sc[nt], qa[ks], bb);
            }
        }

        const int k0 = i * FBKV;
        if (k0 + FBKV - 1 > q0) {
#pragma unroll
            for (int nt = 0; nt < 8; nt++)
#pragma unroll
                for (int e = 0; e < 4; e++) {
                    const int qg = q0 + wband + g + ((e >> 1) << 3);
                    const int kg = k0 + nt * 8 + tg * 2 + (e & 1);
                    if (kg > qg) sc[nt][e] = -1e30f;
                }
        }

        __syncthreads();

        float corr[2];
#pragma unroll
        for (int r2 = 0; r2 < 2; r2++) {
            float tm = -1e30f;
#pragma unroll
            for (int nt = 0; nt < 8; nt++)
                tm = fmaxf(tm, fmaxf(sc[nt][r2 * 2], sc[nt][r2 * 2 + 1]));
            tm = fmaxf(tm, __shfl_xor_sync(0xffffffffu, tm, 1));
            tm = fmaxf(tm, __shfl_xor_sync(0xffffffffu, tm, 2));
            const float mn = fmaxf(m[r2], tm);
            corr[r2] = exp2f(m[r2] - mn);
            m[r2] = mn;
            float s2 = 0.f;
            const int prow = offP + (wband + g + r2 * 8) * VW_S;
#pragma unroll
            for (int nt = 0; nt < 8; nt++) {
                float p0 = exp2f(sc[nt][r2 * 2]     - mn);
                float p1 = exp2f(sc[nt][r2 * 2 + 1] - mn);
                __half2 hp = __floats2half2_rn(p0, p1);
                float2 pr = __half22float2(hp);
                s2 += pr.x + pr.y;
                fsw[prow + nt * 4 + tg] = *(uint32_t*)&hp;
            }
            s2 += __shfl_xor_sync(0xffffffffu, s2, 1);
            s2 += __shfl_xor_sync(0xffffffffu, s2, 2);
            l[r2] = l[r2] * corr[r2] + s2;
        }

#pragma unroll
        for (int nt = 0; nt < 16; nt++) {
            O[nt][0] *= corr[0]; O[nt][1] *= corr[0];
            O[nt][2] *= corr[1]; O[nt][3] *= corr[1];
        }
        __syncwarp();

#pragma unroll
        for (int ks = 0; ks < 4; ks++) {
            const int kb = ks * 8;
            uint32_t a[4];
            {
                const uint32_t* p = &fsw[offP + (wband + g) * VW_S + kb + tg];
                a[0] = p[0];
                a[1] = p[8 * VW_S];
                a[2] = p[4];
                a[3] = p[8 * VW_S + 4];
            }
#pragma unroll
            for (int nt = 0; nt < 16; nt++) {
                const uint32_t* pv = &fsw[offV + (nt * 8 + g) * VW_S + kb + tg];
                uint32_t bb[2] = {pv[0], pv[4]};
                mma_f16(O[nt], a, bb);
            }
        }
    }

    const float inv0 = 1.f / l[0];
    const float inv1 = 1.f / l[1];
    const int row0 = q0 + wband + g;
    __half* base0 = ctx + (((size_t)b * Sq + row0) * HQn + h) * Dh;
    __half* base1 = base0 + (size_t)8 * HQn * Dh;
#pragma unroll
    for (int nt = 0; nt < 16; nt++) {
        const int col = nt * 8 + tg * 2;
        *(__half2*)&base0[col] = __floats2half2_rn(O[nt][0] * inv0,
                                                   O[nt][1] * inv0);
        *(__half2*)&base1[col] = __floats2half2_rn(O[nt][2] * inv1,
                                                   O[nt][3] * inv1);
    }
}

// ---------------------------------------------------------------------------
// Launch
// ---------------------------------------------------------------------------
extern "C" void kernel_launch(void* const* d_in, const int* in_sizes, int n_in,
                              void* d_out, int out_size) {
    const float* hidden = (const float*)d_in[0];
    const float* cosb   = (const float*)d_in[1];
    const float* sinb   = (const float*)d_in[2];
    const float* Wq = (const float*)d_in[4];
    const float* Wk = (const float*)d_in[5];
    const float* Wv = (const float*)d_in[6];
    const float* Wo = (const float*)d_in[7];
    const float* qw = (const float*)d_in[8];
    const float* kw = (const float*)d_in[9];
    float* out = (float*)d_out;

    __half *qb, *kb, *vb, *cb, *hidH, *wqkvT, *woT, *vtb;
    cudaGetSymbolAddress((void**)&qb, g_qH);
    cudaGetSymbolAddress((void**)&kb, g_kH);
    cudaGetSymbolAddress((void**)&vb, g_vH);
    cudaGetSymbolAddress((void**)&cb, g_ctxH);
    cudaGetSymbolAddress((void**)&hidH, g_hidH);
    cudaGetSymbolAddress((void**)&wqkvT, g_WqkvT);
    cudaGetSymbolAddress((void**)&woT, g_WoT);
    cudaGetSymbolAddress((void**)&vtb, g_vT);

    // q scale = 1/sqrt(128) * log2(e)  (exp2-domain softmax)
    const float qscale = 0.088388347648318447f * 1.4426950408889634f;
    const int NPERS = 296;                      // 148 SMs x occupancy 2

    // Fused prep: hidden cvt + all weight transposes (packed grid)
    prep_kernel<<<PREP_GRID, 256>>>(
        hidden, hidH, Wq, Wk, Wv, Wo, wqkvT, woT);

    cudaFuncSetAttribute((const void*)gemm_f16<1, __half>,
                         cudaFuncAttributeMaxDynamicSharedMemorySize, GEMM_SMEM);
    cudaFuncSetAttribute((const void*)gemm_f16<0, float>,
                         cudaFuncAttributeMaxDynamicSharedMemorySize, GEMM_SMEM);

    // Fused QKV projection (persistent; 128x128 tiles: 768 over 296 CTAs)
    gemm_f16<1, __half><<<NPERS, 256, GEMM_SMEM>>>(
        hidH, wqkvT, Hd, 768, 24, qb, kb, vb);

    // RMSNorm+RoPE (q,k; 4 rows/warp) + V transpose (packed grid)
    postqkv_kernel<<<NORM_BLOCKS + VT_BLOCKS, 256>>>(
        qb, kb, vb, vtb, qw, kw, cosb, sinb, qscale);

    // Flash attention (1D LPT grid)
    cudaFuncSetAttribute(flash_mma_kernel,
                         cudaFuncAttributeMaxDynamicSharedMemorySize, FLASH_SMEM);
    flash_mma_kernel<<<(Sq / FBQ) * Bq * HQn, 128, FLASH_SMEM>>>(
        qb, kb, vtb, cb);

    // Output projection (persistent; 128x128 tiles: 512 over 296 CTAs)
    gemm_f16<0, float><<<NPERS, 256, GEMM_SMEM>>>(
        cb, woT, HQn * Dh, 512, 16, out, nullptr, nullptr);
}